// round 14
// baseline (speedup 1.0000x reference)
#include <cuda_runtime.h>
#include <cuda_bf16.h>
#include <cstdint>
#include <cstddef>

#define NN     4096
#define IND    128
#define OUTD   64
#define KSPLIT 4
#define MTILE  128
#define KTILE  128

// ---------------- scratch (device globals; no allocation allowed) ----------
__device__ __align__(16) __nv_bfloat16 g_Wh[2][NN][OUTD];   // Wh, bf16 row-major
__device__ __align__(16) float g_si[2][NN];                 // pre-scaled by log2(e)
__device__ __align__(16) float g_sj[2][NN];                 // pre-scaled by log2(e)
__device__ float g_num[2][KSPLIT][NN * OUTD];               // partial numerators
__device__ float g_Z[2][KSPLIT][NN];                        // partial row sums

__device__ __forceinline__ uint32_t smem_u32(const void* p) {
    return (uint32_t)__cvta_generic_to_shared(p);
}
__device__ __forceinline__ void cp16(uint32_t dst, const void* src) {
    asm volatile("cp.async.cg.shared.global [%0], [%1], 16;" :: "r"(dst), "l"(src));
}
__device__ __forceinline__ void cp_commit() {
    asm volatile("cp.async.commit_group;" ::: "memory");
}
__device__ __forceinline__ void cp_wait0() {
    asm volatile("cp.async.wait_group 0;" ::: "memory");
}

// ---------------- prep: Wh = H@W (fp32) -> bf16; s_i, s_j -------------------
// (measured-best version, 10.9us)
__global__ void __launch_bounds__(256) gat_prep(
    const float* __restrict__ H, const float* __restrict__ W0,
    const float* __restrict__ W1, const float* __restrict__ a0,
    const float* __restrict__ a1)
{
    const int rel = blockIdx.y;
    const int i0  = blockIdx.x * 32;
    const float* __restrict__ W  = rel ? W1 : W0;
    const float* __restrict__ av = rel ? a1 : a0;

    __shared__ __align__(16) float Hs[32][132];
    __shared__ __align__(16) float Ws[IND][68];
    __shared__ float as_[2 * OUTD];

    const int tid = threadIdx.x;

#pragma unroll
    for (int q = 0; q < 4; ++q) {
        int id = q * 256 + tid;
        int r = id >> 5, c4 = id & 31;
        cp16(smem_u32(&Hs[r][c4 * 4]), H + (size_t)(i0 + r) * IND + c4 * 4);
    }
#pragma unroll
    for (int q = 0; q < 8; ++q) {
        int id = q * 256 + tid;
        int k = id >> 4, c4 = id & 15;
        cp16(smem_u32(&Ws[k][c4 * 4]), W + (size_t)k * OUTD + c4 * 4);
    }
    cp_commit();
    if (tid < 2 * OUTD) as_[tid] = av[tid];
    cp_wait0();
    __syncthreads();

    const int tx = tid & 15, ty = tid >> 4;
    float acc[2][4] = {};
#pragma unroll 8
    for (int k = 0; k < IND; ++k) {
        float4 b = *(const float4*)&Ws[k][tx * 4];
        float h0 = Hs[ty * 2 + 0][k];
        float h1 = Hs[ty * 2 + 1][k];
        acc[0][0] += h0 * b.x; acc[0][1] += h0 * b.y;
        acc[0][2] += h0 * b.z; acc[0][3] += h0 * b.w;
        acc[1][0] += h1 * b.x; acc[1][1] += h1 * b.y;
        acc[1][2] += h1 * b.z; acc[1][3] += h1 * b.w;
    }

    float alo[4], ahi[4];
#pragma unroll
    for (int c = 0; c < 4; ++c) {
        alo[c] = as_[tx * 4 + c];
        ahi[c] = as_[OUTD + tx * 4 + c];
    }
    const float LOG2E = 1.4426950408889634f;
#pragma unroll
    for (int r = 0; r < 2; ++r) {
        int gi = i0 + ty * 2 + r;
        __nv_bfloat162 lo = __floats2bfloat162_rn(acc[r][0], acc[r][1]);
        __nv_bfloat162 hi = __floats2bfloat162_rn(acc[r][2], acc[r][3]);
        *(uint2*)&g_Wh[rel][gi][tx * 4] = make_uint2(*(uint32_t*)&lo, *(uint32_t*)&hi);
        float psi = acc[r][0]*alo[0] + acc[r][1]*alo[1] + acc[r][2]*alo[2] + acc[r][3]*alo[3];
        float psj = acc[r][0]*ahi[0] + acc[r][1]*ahi[1] + acc[r][2]*ahi[2] + acc[r][3]*ahi[3];
#pragma unroll
        for (int o = 8; o; o >>= 1) {
            psi += __shfl_down_sync(0xffffffffu, psi, o, 16);
            psj += __shfl_down_sync(0xffffffffu, psj, o, 16);
        }
        if (tx == 0) { g_si[rel][gi] = psi * LOG2E; g_sj[rel][gi] = psj * LOG2E; }
    }
}

// ---------------- main: fused masked-exp + P@Wh via mma.sync ---------------
// Round-12 measured-best structure; ONLY change: KTILE 64->128 (8 barriers
// instead of 16). Mask ring stays 4 f-steps deep, indexed f&3, refilled at
// f+4 (compile-time address selection; f-loop fully unrolled).
__device__ __forceinline__ float lrexp2(float t, int m) {
    t = fmaxf(t, 0.2f * t);
    t = m ? t : -31.0f;
    float e;
    asm("ex2.approx.f32 %0, %1;" : "=f"(e) : "f"(t));
    return e;
}
__device__ __forceinline__ uint32_t packbf2(float lo, float hi) {
    __nv_bfloat162 v = __floats2bfloat162_rn(lo, hi);
    return *(uint32_t*)&v;
}
__device__ __forceinline__ void mma16816(float* c, uint32_t a0, uint32_t a1,
                                         uint32_t a2, uint32_t a3,
                                         uint32_t b0, uint32_t b1) {
    asm volatile("mma.sync.aligned.m16n8k16.row.col.f32.bf16.bf16.f32 "
                 "{%0,%1,%2,%3}, {%4,%5,%6,%7}, {%8,%9}, {%0,%1,%2,%3};"
                 : "+f"(c[0]), "+f"(c[1]), "+f"(c[2]), "+f"(c[3])
                 : "r"(a0), "r"(a1), "r"(a2), "r"(a3), "r"(b0), "r"(b1));
}
__device__ __forceinline__ int perm16(int c) {   // fragment slot -> global offset
    return (c & 1) + ((c >> 1) & 3) * 4 + ((c >> 3) & 1) * 2;
}

__global__ void __launch_bounds__(256, 2) gat_main(const int* __restrict__ A0,
                                                   const int* __restrict__ A1)
{
    __shared__ __align__(16) __nv_bfloat16 Bs[2][KTILE][72];  // 36.9 KB
    __shared__ __align__(16) float sjs[NN / KSPLIT];          // 4 KB

    const int i0  = blockIdx.x * MTILE;
    const int ksp = blockIdx.y;
    const int rel = blockIdx.z;
    const int* __restrict__ A = rel ? A1 : A0;

    const int tid = threadIdx.x;
    const int w = tid >> 5, lane = tid & 31;
    const int kbase = ksp * (NN / KSPLIT);

    for (int i = tid; i < NN / KSPLIT; i += 256) sjs[i] = g_sj[rel][kbase + i];

    const int r  = lane >> 2;            // 0..7
    const int q  = lane & 3;             // col quad
    const int c0 = q * 2;                // fragment col pair base
    const int row0 = i0 + w * 16 + r;
    const int row1 = row0 + 8;
    const float si0 = g_si[rel][row0];
    const float si1 = g_si[rel][row1];
    const int* __restrict__ Ar0 = A + (size_t)row0 * NN;
    const int* __restrict__ Ar1 = A + (size_t)row1 * NN;

    float acc[8][4];
#pragma unroll
    for (int nt = 0; nt < 8; ++nt)
#pragma unroll
        for (int qq = 0; qq < 4; ++qq) acc[nt][qq] = 0.f;
    float z0 = 0.f, z1 = 0.f;

    const __nv_bfloat16* __restrict__ whb = &g_Wh[rel][0][0];
    const int ntiles = (NN / KSPLIT) / KTILE;        // 8

    // Bs staging: 128 rows x 64 cols bf16 = 1024 x 16B chunks; 4 per thread.
    const int stg_kr = tid >> 3, stg_ch = tid & 7;   // rows 0..31 (+32*qq)

    // 4-f-step mask ring (slot = f & 3), prologue loads f=0..3 of tile 0
    int4 mb0[4], mb1[4];
#pragma unroll
    for (int f = 0; f < 4; ++f) {
        const int gc = kbase + f * 16 + q * 4;
        mb0[f] = *(const int4*)(Ar0 + gc);
        mb1[f] = *(const int4*)(Ar1 + gc);
    }

    // prologue: async-stage Bs tile 0 into buffer 0 (permuted rows)
#pragma unroll
    for (int qq = 0; qq < 4; ++qq) {
        const int kr = stg_kr + qq * 32;
        const int src = (kr & 112) | perm16(kr & 15);
        cp16(smem_u32(&Bs[0][kr][stg_ch * 8]),
             whb + (size_t)(kbase + src) * OUTD + stg_ch * 8);
    }
    cp_commit();
    cp_wait0();
    __syncthreads();

    for (int t = 0; t < ntiles; ++t) {
        const int buf = t & 1;

        if (t + 1 < ntiles) {
            const int kn = kbase + (t + 1) * KTILE;
#pragma unroll
            for (int qq = 0; qq < 4; ++qq) {
                const int kr = stg_kr + qq * 32;
                const int src = (kr & 112) | perm16(kr & 15);
                cp16(smem_u32(&Bs[buf ^ 1][kr][stg_ch * 8]),
                     whb + (size_t)(kn + src) * OUTD + stg_ch * 8);
            }
            cp_commit();
        }

#pragma unroll
        for (int f = 0; f < 8; ++f) {
            const int sl = f & 3;
            int4 m0 = mb0[sl], m1 = mb1[sl];
            // refill slot with step f+4 (same tile if f<4, else next tile)
            if (f < 4) {
                const int gc = kbase + t * KTILE + (f + 4) * 16 + q * 4;
                mb0[sl] = *(const int4*)(Ar0 + gc);
                mb1[sl] = *(const int4*)(Ar1 + gc);
            } else if (t + 1 < ntiles) {
                const int gc = kbase + (t + 1) * KTILE + (f - 4) * 16 + q * 4;
                mb0[sl] = *(const int4*)(Ar0 + gc);
                mb1[sl] = *(const int4*)(Ar1 + gc);
            }

            float4 sj4 = *(const float4*)&sjs[t * KTILE + f * 16 + q * 4];

            float p0a = lrexp2(si0 + sj4.x, m0.x);
            float p0b = lrexp2(si0 + sj4.y, m0.y);
            float p0c = lrexp2(si0 + sj4.z, m0.z);
            float p0d = lrexp2(si0 + sj4.w, m0.w);
            float p1a = lrexp2(si1 + sj4.x, m1.x);
            float p1b = lrexp2(si1 + sj4.y, m1.y);
            float p1c = lrexp2(si1 + sj4.z, m1.z);
            float p1d = lrexp2(si1 + sj4.w, m1.w);
            z0 += p0a + p0b + p0c + p0d;
            z1 += p1a + p1b + p1c + p1d;

            uint32_t a0 = packbf2(p0a, p0b);
            uint32_t a1 = packbf2(p1a, p1b);
            uint32_t a2 = packbf2(p0c, p0d);
            uint32_t a3 = packbf2(p1c, p1d);

#pragma unroll
            for (int nt = 0; nt < 4; ++nt) {
                uint32_t b0, b1, b2, b3;
                uint32_t addr = smem_u32(
                    &Bs[buf][f * 16 + (lane & 15)][nt * 16 + (lane >> 4) * 8]);
                asm volatile(
                    "ldmatrix.sync.aligned.m8n8.x4.trans.shared.b16 "
                    "{%0,%1,%2,%3}, [%4];"
                    : "=r"(b0), "=r"(b1), "=r"(b2), "=r"(b3) : "r"(addr));
                mma16816(acc[2 * nt],     a0, a1, a2, a3, b0, b1);
                mma16816(acc[2 * nt + 1], a0, a1, a2, a3, b2, b3);
            }
        }

        if (t + 1 < ntiles) cp_wait0();
        __syncthreads();
    }

    // Z: reduce within quad
    z0 += __shfl_xor_sync(0xffffffffu, z0, 1);
    z0 += __shfl_xor_sync(0xffffffffu, z0, 2);
    z1 += __shfl_xor_sync(0xffffffffu, z1, 1);
    z1 += __shfl_xor_sync(0xffffffffu, z1, 2);
    if ((lane & 3) == 0) {
        g_Z[rel][ksp][row0] = z0;
        g_Z[rel][ksp][row1] = z1;
    }

    float* __restrict__ num = &g_num[rel][ksp][0];
#pragma unroll
    for (int nt = 0; nt < 8; ++nt) {
        int col = nt * 8 + c0;
        *(float2*)&num[(size_t)row0 * OUTD + col] = make_float2(acc[nt][0], acc[nt][1]);
        *(float2*)&num[(size_t)row1 * OUTD + col] = make_float2(acc[nt][2], acc[nt][3]);
    }
}

// ---------------- combine: out = sum_rel num/Z + bias (float4) --------------
__global__ void __launch_bounds__(256) gat_combine(const float* __restrict__ bias,
                                                   float* __restrict__ out)
{
    const int idx4 = blockIdx.x * 256 + threadIdx.x;   // 65536 total
    const int base = idx4 * 4;
    const int i = base >> 6, cc = base & 63;
    float4 r = *(const float4*)(bias + cc);
#pragma unroll
    for (int rel = 0; rel < 2; ++rel) {
        float4 ns = make_float4(0.f, 0.f, 0.f, 0.f);
        float zs = 0.f;
#pragma unroll
        for (int ks = 0; ks < KSPLIT; ++ks) {
            float4 v = *(const float4*)&g_num[rel][ks][base];
            ns.x += v.x; ns.y += v.y; ns.z += v.z; ns.w += v.w;
            zs += g_Z[rel][ks][i];
        }
        float inv = (zs > 0.f) ? __frcp_rn(zs) : 0.f;
        r.x += ns.x * inv; r.y += ns.y * inv;
        r.z += ns.z * inv; r.w += ns.w * inv;
    }
    *(float4*)(out + base) = r;
}

// ---------------- launch ----------------------------------------------------
extern "C" void kernel_launch(void* const* d_in, const int* in_sizes, int n_in,
                              void* d_out, int out_size) {
    const float* H    = (const float*)d_in[0];
    const int*   A0   = (const int*)  d_in[1];
    const int*   A1   = (const int*)  d_in[2];
    const float* W0   = (const float*)d_in[3];
    const float* W1   = (const float*)d_in[4];
    const float* a0   = (const float*)d_in[5];
    const float* a1   = (const float*)d_in[6];
    const float* bias = (const float*)d_in[7];
    float* out = (float*)d_out;

    gat_prep<<<dim3(NN / 32, 2), 256>>>(H, W0, W1, a0, a1);
    gat_main<<<dim3(NN / MTILE, KSPLIT, 2), 256>>>(A0, A1);
    gat_combine<<<(NN * OUTD) / 1024, 256>>>(bias, out);
}

// round 15
// speedup vs baseline: 1.4090x; 1.4090x over previous
#include <cuda_runtime.h>
#include <cuda_bf16.h>
#include <cstdint>
#include <cstddef>

#define NN     4096
#define IND    128
#define OUTD   64
#define KSPLIT 4
#define MTILE  128
#define KTILE  64

// ---------------- scratch (device globals; no allocation allowed) ----------
__device__ __align__(16) __nv_bfloat16 g_Wh[2][NN][OUTD];   // Wh, bf16 row-major
__device__ __align__(16) float g_si[2][NN];                 // pre-scaled by log2(e)
__device__ __align__(16) float g_sj[2][NN];                 // pre-scaled by log2(e)
__device__ float g_num[2][KSPLIT][NN * OUTD];               // partial numerators
__device__ float g_Z[2][KSPLIT][NN];                        // partial row sums

__device__ __forceinline__ uint32_t smem_u32(const void* p) {
    return (uint32_t)__cvta_generic_to_shared(p);
}
__device__ __forceinline__ void cp16(uint32_t dst, const void* src) {
    asm volatile("cp.async.cg.shared.global [%0], [%1], 16;" :: "r"(dst), "l"(src));
}
__device__ __forceinline__ void cp_commit() {
    asm volatile("cp.async.commit_group;" ::: "memory");
}
__device__ __forceinline__ void cp_wait0() {
    asm volatile("cp.async.wait_group 0;" ::: "memory");
}

// ---------------- prep: Wh = H@W (fp32) -> bf16; s_i, s_j -------------------
__global__ void __launch_bounds__(256) gat_prep(
    const float* __restrict__ H, const float* __restrict__ W0,
    const float* __restrict__ W1, const float* __restrict__ a0,
    const float* __restrict__ a1)
{
    const int rel = blockIdx.y;
    const int i0  = blockIdx.x * 32;
    const float* __restrict__ W  = rel ? W1 : W0;
    const float* __restrict__ av = rel ? a1 : a0;

    __shared__ __align__(16) float Hs[32][132];
    __shared__ __align__(16) float Ws[IND][68];
    __shared__ float as_[2 * OUTD];

    const int tid = threadIdx.x;

#pragma unroll
    for (int q = 0; q < 4; ++q) {
        int id = q * 256 + tid;
        int r = id >> 5, c4 = id & 31;
        cp16(smem_u32(&Hs[r][c4 * 4]), H + (size_t)(i0 + r) * IND + c4 * 4);
    }
#pragma unroll
    for (int q = 0; q < 8; ++q) {
        int id = q * 256 + tid;
        int k = id >> 4, c4 = id & 15;
        cp16(smem_u32(&Ws[k][c4 * 4]), W + (size_t)k * OUTD + c4 * 4);
    }
    cp_commit();
    if (tid < 2 * OUTD) as_[tid] = av[tid];
    cp_wait0();
    __syncthreads();

    const int tx = tid & 15, ty = tid >> 4;
    float acc[2][4] = {};
#pragma unroll 8
    for (int k = 0; k < IND; ++k) {
        float4 b = *(const float4*)&Ws[k][tx * 4];
        float h0 = Hs[ty * 2 + 0][k];
        float h1 = Hs[ty * 2 + 1][k];
        acc[0][0] += h0 * b.x; acc[0][1] += h0 * b.y;
        acc[0][2] += h0 * b.z; acc[0][3] += h0 * b.w;
        acc[1][0] += h1 * b.x; acc[1][1] += h1 * b.y;
        acc[1][2] += h1 * b.z; acc[1][3] += h1 * b.w;
    }

    float alo[4], ahi[4];
#pragma unroll
    for (int c = 0; c < 4; ++c) {
        alo[c] = as_[tx * 4 + c];
        ahi[c] = as_[OUTD + tx * 4 + c];
    }
    const float LOG2E = 1.4426950408889634f;
#pragma unroll
    for (int r = 0; r < 2; ++r) {
        int gi = i0 + ty * 2 + r;
        __nv_bfloat162 lo = __floats2bfloat162_rn(acc[r][0], acc[r][1]);
        __nv_bfloat162 hi = __floats2bfloat162_rn(acc[r][2], acc[r][3]);
        *(uint2*)&g_Wh[rel][gi][tx * 4] = make_uint2(*(uint32_t*)&lo, *(uint32_t*)&hi);
        float psi = acc[r][0]*alo[0] + acc[r][1]*alo[1] + acc[r][2]*alo[2] + acc[r][3]*alo[3];
        float psj = acc[r][0]*ahi[0] + acc[r][1]*ahi[1] + acc[r][2]*ahi[2] + acc[r][3]*ahi[3];
#pragma unroll
        for (int o = 8; o; o >>= 1) {
            psi += __shfl_down_sync(0xffffffffu, psi, o, 16);
            psj += __shfl_down_sync(0xffffffffu, psj, o, 16);
        }
        if (tx == 0) { g_si[rel][gi] = psi * LOG2E; g_sj[rel][gi] = psj * LOG2E; }
    }
}

// ---------------- main: fused masked-exp + P@Wh via mma.sync ---------------
// Measured-best structure (round 12, 47.6us): register A pipeline (full-tile
// lookahead, 32 regs), KTILE=64, cp.async Bs double-buffer, column
// permutation so each f-step needs ONE int4 mask LDG + ONE float4 sj LDS.
__device__ __forceinline__ float lrexp2(float t, int m) {
    t = fmaxf(t, 0.2f * t);
    t = m ? t : -31.0f;
    float e;
    asm("ex2.approx.f32 %0, %1;" : "=f"(e) : "f"(t));
    return e;
}
__device__ __forceinline__ uint32_t packbf2(float lo, float hi) {
    __nv_bfloat162 v = __floats2bfloat162_rn(lo, hi);
    return *(uint32_t*)&v;
}
__device__ __forceinline__ void mma16816(float* c, uint32_t a0, uint32_t a1,
                                         uint32_t a2, uint32_t a3,
                                         uint32_t b0, uint32_t b1) {
    asm volatile("mma.sync.aligned.m16n8k16.row.col.f32.bf16.bf16.f32 "
                 "{%0,%1,%2,%3}, {%4,%5,%6,%7}, {%8,%9}, {%0,%1,%2,%3};"
                 : "+f"(c[0]), "+f"(c[1]), "+f"(c[2]), "+f"(c[3])
                 : "r"(a0), "r"(a1), "r"(a2), "r"(a3), "r"(b0), "r"(b1));
}
__device__ __forceinline__ int perm16(int c) {   // fragment slot -> global offset
    return (c & 1) + ((c >> 1) & 3) * 4 + ((c >> 3) & 1) * 2;
}

__global__ void __launch_bounds__(256, 2) gat_main(const int* __restrict__ A0,
                                                   const int* __restrict__ A1)
{
    __shared__ __align__(16) __nv_bfloat16 Bs[2][KTILE][72];  // ping-pong, +8 pad
    __shared__ __align__(16) float sjs[NN / KSPLIT];          // 4 KB

    const int i0  = blockIdx.x * MTILE;
    const int ksp = blockIdx.y;
    const int rel = blockIdx.z;
    const int* __restrict__ A = rel ? A1 : A0;

    const int tid = threadIdx.x;
    const int w = tid >> 5, lane = tid & 31;
    const int kbase = ksp * (NN / KSPLIT);

    for (int i = tid; i < NN / KSPLIT; i += 256) sjs[i] = g_sj[rel][kbase + i];

    const int r  = lane >> 2;            // 0..7
    const int q  = lane & 3;             // col quad
    const int c0 = q * 2;                // fragment col pair base
    const int row0 = i0 + w * 16 + r;
    const int row1 = row0 + 8;
    const float si0 = g_si[rel][row0];
    const float si1 = g_si[rel][row1];
    const int* __restrict__ Ar0 = A + (size_t)row0 * NN;
    const int* __restrict__ Ar1 = A + (size_t)row1 * NN;

    float acc[8][4];
#pragma unroll
    for (int nt = 0; nt < 8; ++nt)
#pragma unroll
        for (int qq = 0; qq < 4; ++qq) acc[nt][qq] = 0.f;
    float z0 = 0.f, z1 = 0.f;

    const __nv_bfloat16* __restrict__ whb = &g_Wh[rel][0][0];
    const int ntiles = (NN / KSPLIT) / KTILE;        // 16

    // Bs staging coords with permuted source rows
    const int stg_kr = tid >> 3, stg_ch = tid & 7;
    const int src_a = (stg_kr & 48) | perm16(stg_kr & 15);
    const int src_b = ((stg_kr + 32) & 48) | perm16(stg_kr & 15);

    // A-mask register pipeline: int4 per row per f-step (global cols 4q..4q+3)
    int4 mb0[4], mb1[4];
#pragma unroll
    for (int f = 0; f < 4; ++f) {
        const int gc = kbase + f * 16 + q * 4;
        mb0[f] = *(const int4*)(Ar0 + gc);
        mb1[f] = *(const int4*)(Ar1 + gc);
    }

    // prologue: async-stage Bs tile 0 into buffer 0 (permuted rows)
    cp16(smem_u32(&Bs[0][stg_kr][stg_ch * 8]),
         whb + (size_t)(kbase + src_a) * OUTD + stg_ch * 8);
    cp16(smem_u32(&Bs[0][stg_kr + 32][stg_ch * 8]),
         whb + (size_t)(kbase + src_b) * OUTD + stg_ch * 8);
    cp_commit();
    cp_wait0();
    __syncthreads();

    for (int t = 0; t < ntiles; ++t) {
        const int buf = t & 1;

        if (t + 1 < ntiles) {
            const int kn = kbase + (t + 1) * KTILE;
            cp16(smem_u32(&Bs[buf ^ 1][stg_kr][stg_ch * 8]),
                 whb + (size_t)(kn + src_a) * OUTD + stg_ch * 8);
            cp16(smem_u32(&Bs[buf ^ 1][stg_kr + 32][stg_ch * 8]),
                 whb + (size_t)(kn + src_b) * OUTD + stg_ch * 8);
            cp_commit();
        }

#pragma unroll
        for (int f = 0; f < 4; ++f) {
            int4 m0 = mb0[f], m1 = mb1[f];
            if (t + 1 < ntiles) {
                const int gc = kbase + (t + 1) * KTILE + f * 16 + q * 4;
                mb0[f] = *(const int4*)(Ar0 + gc);
                mb1[f] = *(const int4*)(Ar1 + gc);
            }

            float4 sj4 = *(const float4*)&sjs[t * KTILE + f * 16 + q * 4];

            float p0a = lrexp2(si0 + sj4.x, m0.x);
            float p0b = lrexp2(si0 + sj4.y, m0.y);
            float p0c = lrexp2(si0 + sj4.z, m0.z);
            float p0d = lrexp2(si0 + sj4.w, m0.w);
            float p1a = lrexp2(si1 + sj4.x, m1.x);
            float p1b = lrexp2(si1 + sj4.y, m1.y);
            float p1c = lrexp2(si1 + sj4.z, m1.z);
            float p1d = lrexp2(si1 + sj4.w, m1.w);
            z0 += p0a + p0b + p0c + p0d;
            z1 += p1a + p1b + p1c + p1d;

            uint32_t a0 = packbf2(p0a, p0b);
            uint32_t a1 = packbf2(p1a, p1b);
            uint32_t a2 = packbf2(p0c, p0d);
            uint32_t a3 = packbf2(p1c, p1d);

#pragma unroll
            for (int nt = 0; nt < 4; ++nt) {
                uint32_t b0, b1, b2, b3;
                uint32_t addr = smem_u32(
                    &Bs[buf][f * 16 + (lane & 15)][nt * 16 + (lane >> 4) * 8]);
                asm volatile(
                    "ldmatrix.sync.aligned.m8n8.x4.trans.shared.b16 "
                    "{%0,%1,%2,%3}, [%4];"
                    : "=r"(b0), "=r"(b1), "=r"(b2), "=r"(b3) : "r"(addr));
                mma16816(acc[2 * nt],     a0, a1, a2, a3, b0, b1);
                mma16816(acc[2 * nt + 1], a0, a1, a2, a3, b2, b3);
            }
        }

        if (t + 1 < ntiles) cp_wait0();
        __syncthreads();
    }

    // Z: reduce within quad
    z0 += __shfl_xor_sync(0xffffffffu, z0, 1);
    z0 += __shfl_xor_sync(0xffffffffu, z0, 2);
    z1 += __shfl_xor_sync(0xffffffffu, z1, 1);
    z1 += __shfl_xor_sync(0xffffffffu, z1, 2);
    if ((lane & 3) == 0) {
        g_Z[rel][ksp][row0] = z0;
        g_Z[rel][ksp][row1] = z1;
    }

    float* __restrict__ num = &g_num[rel][ksp][0];
#pragma unroll
    for (int nt = 0; nt < 8; ++nt) {
        int col = nt * 8 + c0;
        *(float2*)&num[(size_t)row0 * OUTD + col] = make_float2(acc[nt][0], acc[nt][1]);
        *(float2*)&num[(size_t)row1 * OUTD + col] = make_float2(acc[nt][2], acc[nt][3]);
    }
}

// ---------------- combine: out = sum_rel num/Z + bias (float4) --------------
__global__ void __launch_bounds__(256) gat_combine(const float* __restrict__ bias,
                                                   float* __restrict__ out)
{
    const int idx4 = blockIdx.x * 256 + threadIdx.x;   // 65536 total
    const int base = idx4 * 4;
    const int i = base >> 6, cc = base & 63;
    float4 r = *(const float4*)(bias + cc);
#pragma unroll
    for (int rel = 0; rel < 2; ++rel) {
        float4 ns = make_float4(0.f, 0.f, 0.f, 0.f);
        float zs = 0.f;
#pragma unroll
        for (int ks = 0; ks < KSPLIT; ++ks) {
            float4 v = *(const float4*)&g_num[rel][ks][base];
            ns.x += v.x; ns.y += v.y; ns.z += v.z; ns.w += v.w;
            zs += g_Z[rel][ks][i];
        }
        float inv = (zs > 0.f) ? __frcp_rn(zs) : 0.f;
        r.x += ns.x * inv; r.y += ns.y * inv;
        r.z += ns.z * inv; r.w += ns.w * inv;
    }
    *(float4*)(out + base) = r;
}

// ---------------- launch ----------------------------------------------------
extern "C" void kernel_launch(void* const* d_in, const int* in_sizes, int n_in,
                              void* d_out, int out_size) {
    const float* H    = (const float*)d_in[0];
    const int*   A0   = (const int*)  d_in[1];
    const int*   A1   = (const int*)  d_in[2];
    const float* W0   = (const float*)d_in[3];
    const float* W1   = (const float*)d_in[4];
    const float* a0   = (const float*)d_in[5];
    const float* a1   = (const float*)d_in[6];
    const float* bias = (const float*)d_in[7];
    float* out = (float*)d_out;

    gat_prep<<<dim3(NN / 32, 2), 256>>>(H, W0, W1, a0, a1);
    gat_main<<<dim3(NN / MTILE, KSPLIT, 2), 256>>>(A0, A1);
    gat_combine<<<(NN * OUTD) / 1024, 256>>>(bias, out);
}

// round 17
// speedup vs baseline: 1.4501x; 1.0292x over previous
#include <cuda_runtime.h>
#include <cuda_bf16.h>
#include <cstdint>
#include <cstddef>

#define NN     4096
#define IND    128
#define OUTD   64
#define KSPLIT 4
#define MTILE  128
#define KTILE  64

// ---------------- scratch (device globals; no allocation allowed) ----------
__device__ __align__(16) __nv_bfloat16 g_Wh[2][NN][OUTD];   // Wh, bf16 row-major
__device__ __align__(16) float g_si[2][NN];                 // pre-scaled by log2(e)
__device__ __align__(16) float g_sj[2][NN];                 // pre-scaled by log2(e)
__device__ float g_num[2][KSPLIT][NN * OUTD];               // partial numerators
__device__ float g_Z[2][KSPLIT][NN];                        // partial row sums

__device__ __forceinline__ uint32_t smem_u32(const void* p) {
    return (uint32_t)__cvta_generic_to_shared(p);
}
__device__ __forceinline__ void cp16(uint32_t dst, const void* src) {
    asm volatile("cp.async.cg.shared.global [%0], [%1], 16;" :: "r"(dst), "l"(src));
}
__device__ __forceinline__ void cp_commit() {
    asm volatile("cp.async.commit_group;" ::: "memory");
}
__device__ __forceinline__ void cp_wait0() {
    asm volatile("cp.async.wait_group 0;" ::: "memory");
}
// L2 evict-first policy for the zero-reuse A mask stream (keeps the 4x-reused
// Wh working set resident in L2). createpolicy + cache_hint is the encoding
// ptxas accepts for 16B vector loads.
__device__ __forceinline__ uint64_t mk_evict_first_policy() {
    uint64_t pol;
    asm("createpolicy.fractional.L2::evict_first.b64 %0, 1.0;" : "=l"(pol));
    return pol;
}
__device__ __forceinline__ int4 ldg_stream4(const int* p, uint64_t pol) {
    int4 v;
    asm volatile("ld.global.nc.L2::cache_hint.v4.u32 {%0,%1,%2,%3}, [%4], %5;"
                 : "=r"(v.x), "=r"(v.y), "=r"(v.z), "=r"(v.w)
                 : "l"(p), "l"(pol));
    return v;
}

// ---------------- prep: Wh = H@W (fp32) -> bf16; s_i, s_j -------------------
__global__ void __launch_bounds__(256) gat_prep(
    const float* __restrict__ H, const float* __restrict__ W0,
    const float* __restrict__ W1, const float* __restrict__ a0,
    const float* __restrict__ a1)
{
    const int rel = blockIdx.y;
    const int i0  = blockIdx.x * 32;
    const float* __restrict__ W  = rel ? W1 : W0;
    const float* __restrict__ av = rel ? a1 : a0;

    __shared__ __align__(16) float Hs[32][132];
    __shared__ __align__(16) float Ws[IND][68];
    __shared__ float as_[2 * OUTD];

    const int tid = threadIdx.x;

#pragma unroll
    for (int q = 0; q < 4; ++q) {
        int id = q * 256 + tid;
        int r = id >> 5, c4 = id & 31;
        cp16(smem_u32(&Hs[r][c4 * 4]), H + (size_t)(i0 + r) * IND + c4 * 4);
    }
#pragma unroll
    for (int q = 0; q < 8; ++q) {
        int id = q * 256 + tid;
        int k = id >> 4, c4 = id & 15;
        cp16(smem_u32(&Ws[k][c4 * 4]), W + (size_t)k * OUTD + c4 * 4);
    }
    cp_commit();
    if (tid < 2 * OUTD) as_[tid] = av[tid];
    cp_wait0();
    __syncthreads();

    const int tx = tid & 15, ty = tid >> 4;
    float acc[2][4] = {};
#pragma unroll 8
    for (int k = 0; k < IND; ++k) {
        float4 b = *(const float4*)&Ws[k][tx * 4];
        float h0 = Hs[ty * 2 + 0][k];
        float h1 = Hs[ty * 2 + 1][k];
        acc[0][0] += h0 * b.x; acc[0][1] += h0 * b.y;
        acc[0][2] += h0 * b.z; acc[0][3] += h0 * b.w;
        acc[1][0] += h1 * b.x; acc[1][1] += h1 * b.y;
        acc[1][2] += h1 * b.z; acc[1][3] += h1 * b.w;
    }

    float alo[4], ahi[4];
#pragma unroll
    for (int c = 0; c < 4; ++c) {
        alo[c] = as_[tx * 4 + c];
        ahi[c] = as_[OUTD + tx * 4 + c];
    }
    const float LOG2E = 1.4426950408889634f;
#pragma unroll
    for (int r = 0; r < 2; ++r) {
        int gi = i0 + ty * 2 + r;
        __nv_bfloat162 lo = __floats2bfloat162_rn(acc[r][0], acc[r][1]);
        __nv_bfloat162 hi = __floats2bfloat162_rn(acc[r][2], acc[r][3]);
        *(uint2*)&g_Wh[rel][gi][tx * 4] = make_uint2(*(uint32_t*)&lo, *(uint32_t*)&hi);
        float psi = acc[r][0]*alo[0] + acc[r][1]*alo[1] + acc[r][2]*alo[2] + acc[r][3]*alo[3];
        float psj = acc[r][0]*ahi[0] + acc[r][1]*ahi[1] + acc[r][2]*ahi[2] + acc[r][3]*ahi[3];
#pragma unroll
        for (int o = 8; o; o >>= 1) {
            psi += __shfl_down_sync(0xffffffffu, psi, o, 16);
            psj += __shfl_down_sync(0xffffffffu, psj, o, 16);
        }
        if (tx == 0) { g_si[rel][gi] = psi * LOG2E; g_sj[rel][gi] = psj * LOG2E; }
    }
}

// ---------------- main: fused masked-exp + P@Wh via mma.sync ---------------
// Measured-best structure (round 12, 47.6us). ONLY change: A mask loads use
// L2::evict_first via createpolicy+cache_hint (zero-reuse stream; protects
// Wh L2 residency).
__device__ __forceinline__ float lrexp2(float t, int m) {
    t = fmaxf(t, 0.2f * t);
    t = m ? t : -31.0f;
    float e;
    asm("ex2.approx.f32 %0, %1;" : "=f"(e) : "f"(t));
    return e;
}
__device__ __forceinline__ uint32_t packbf2(float lo, float hi) {
    __nv_bfloat162 v = __floats2bfloat162_rn(lo, hi);
    return *(uint32_t*)&v;
}
__device__ __forceinline__ void mma16816(float* c, uint32_t a0, uint32_t a1,
                                         uint32_t a2, uint32_t a3,
                                         uint32_t b0, uint32_t b1) {
    asm volatile("mma.sync.aligned.m16n8k16.row.col.f32.bf16.bf16.f32 "
                 "{%0,%1,%2,%3}, {%4,%5,%6,%7}, {%8,%9}, {%0,%1,%2,%3};"
                 : "+f"(c[0]), "+f"(c[1]), "+f"(c[2]), "+f"(c[3])
                 : "r"(a0), "r"(a1), "r"(a2), "r"(a3), "r"(b0), "r"(b1));
}
__device__ __forceinline__ int perm16(int c) {   // fragment slot -> global offset
    return (c & 1) + ((c >> 1) & 3) * 4 + ((c >> 3) & 1) * 2;
}

__global__ void __launch_bounds__(256, 2) gat_main(const int* __restrict__ A0,
                                                   const int* __restrict__ A1)
{
    __shared__ __align__(16) __nv_bfloat16 Bs[2][KTILE][72];  // ping-pong, +8 pad
    __shared__ __align__(16) float sjs[NN / KSPLIT];          // 4 KB

    const int i0  = blockIdx.x * MTILE;
    const int ksp = blockIdx.y;
    const int rel = blockIdx.z;
    const int* __restrict__ A = rel ? A1 : A0;

    const int tid = threadIdx.x;
    const int w = tid >> 5, lane = tid & 31;
    const int kbase = ksp * (NN / KSPLIT);

    for (int i = tid; i < NN / KSPLIT; i += 256) sjs[i] = g_sj[rel][kbase + i];

    const int r  = lane >> 2;            // 0..7
    const int q  = lane & 3;             // col quad
    const int c0 = q * 2;                // fragment col pair base
    const int row0 = i0 + w * 16 + r;
    const int row1 = row0 + 8;
    const float si0 = g_si[rel][row0];
    const float si1 = g_si[rel][row1];
    const int* __restrict__ Ar0 = A + (size_t)row0 * NN;
    const int* __restrict__ Ar1 = A + (size_t)row1 * NN;
    const uint64_t pol = mk_evict_first_policy();

    float acc[8][4];
#pragma unroll
    for (int nt = 0; nt < 8; ++nt)
#pragma unroll
        for (int qq = 0; qq < 4; ++qq) acc[nt][qq] = 0.f;
    float z0 = 0.f, z1 = 0.f;

    const __nv_bfloat16* __restrict__ whb = &g_Wh[rel][0][0];
    const int ntiles = (NN / KSPLIT) / KTILE;        // 16

    // Bs staging coords with permuted source rows
    const int stg_kr = tid >> 3, stg_ch = tid & 7;
    const int src_a = (stg_kr & 48) | perm16(stg_kr & 15);
    const int src_b = ((stg_kr + 32) & 48) | perm16(stg_kr & 15);

    // A-mask register pipeline: int4 per row per f-step (global cols 4q..4q+3)
    int4 mb0[4], mb1[4];
#pragma unroll
    for (int f = 0; f < 4; ++f) {
        const int gc = kbase + f * 16 + q * 4;
        mb0[f] = ldg_stream4(Ar0 + gc, pol);
        mb1[f] = ldg_stream4(Ar1 + gc, pol);
    }

    // prologue: async-stage Bs tile 0 into buffer 0 (permuted rows)
    cp16(smem_u32(&Bs[0][stg_kr][stg_ch * 8]),
         whb + (size_t)(kbase + src_a) * OUTD + stg_ch * 8);
    cp16(smem_u32(&Bs[0][stg_kr + 32][stg_ch * 8]),
         whb + (size_t)(kbase + src_b) * OUTD + stg_ch * 8);
    cp_commit();
    cp_wait0();
    __syncthreads();

    for (int t = 0; t < ntiles; ++t) {
        const int buf = t & 1;

        if (t + 1 < ntiles) {
            const int kn = kbase + (t + 1) * KTILE;
            cp16(smem_u32(&Bs[buf ^ 1][stg_kr][stg_ch * 8]),
                 whb + (size_t)(kn + src_a) * OUTD + stg_ch * 8);
            cp16(smem_u32(&Bs[buf ^ 1][stg_kr + 32][stg_ch * 8]),
                 whb + (size_t)(kn + src_b) * OUTD + stg_ch * 8);
            cp_commit();
        }

#pragma unroll
        for (int f = 0; f < 4; ++f) {
            int4 m0 = mb0[f], m1 = mb1[f];
            if (t + 1 < ntiles) {
                const int gc = kbase + (t + 1) * KTILE + f * 16 + q * 4;
                mb0[f] = ldg_stream4(Ar0 + gc, pol);
                mb1[f] = ldg_stream4(Ar1 + gc, pol);
            }

            float4 sj4 = *(const float4*)&sjs[t * KTILE + f * 16 + q * 4];

            float p0a = lrexp2(si0 + sj4.x, m0.x);
            float p0b = lrexp2(si0 + sj4.y, m0.y);
            float p0c = lrexp2(si0 + sj4.z, m0.z);
            float p0d = lrexp2(si0 + sj4.w, m0.w);
            float p1a = lrexp2(si1 + sj4.x, m1.x);
            float p1b = lrexp2(si1 + sj4.y, m1.y);
            float p1c = lrexp2(si1 + sj4.z, m1.z);
            float p1d = lrexp2(si1 + sj4.w, m1.w);
            z0 += p0a + p0b + p0c + p0d;
            z1 += p1a + p1b + p1c + p1d;

            uint32_t a0 = packbf2(p0a, p0b);
            uint32_t a1 = packbf2(p1a, p1b);
            uint32_t a2 = packbf2(p0c, p0d);
            uint32_t a3 = packbf2(p1c, p1d);

#pragma unroll
            for (int nt = 0; nt < 4; ++nt) {
                uint32_t b0, b1, b2, b3;
                uint32_t addr = smem_u32(
                    &Bs[buf][f * 16 + (lane & 15)][nt * 16 + (lane >> 4) * 8]);
                asm volatile(
                    "ldmatrix.sync.aligned.m8n8.x4.trans.shared.b16 "
                    "{%0,%1,%2,%3}, [%4];"
                    : "=r"(b0), "=r"(b1), "=r"(b2), "=r"(b3) : "r"(addr));
                mma16816(acc[2 * nt],     a0, a1, a2, a3, b0, b1);
                mma16816(acc[2 * nt + 1], a0, a1, a2, a3, b2, b3);
            }
        }

        if (t + 1 < ntiles) cp_wait0();
        __syncthreads();
    }

    // Z: reduce within quad
    z0 += __shfl_xor_sync(0xffffffffu, z0, 1);
    z0 += __shfl_xor_sync(0xffffffffu, z0, 2);
    z1 += __shfl_xor_sync(0xffffffffu, z1, 1);
    z1 += __shfl_xor_sync(0xffffffffu, z1, 2);
    if ((lane & 3) == 0) {
        g_Z[rel][ksp][row0] = z0;
        g_Z[rel][ksp][row1] = z1;
    }

    float* __restrict__ num = &g_num[rel][ksp][0];
#pragma unroll
    for (int nt = 0; nt < 8; ++nt) {
        int col = nt * 8 + c0;
        *(float2*)&num[(size_t)row0 * OUTD + col] = make_float2(acc[nt][0], acc[nt][1]);
        *(float2*)&num[(size_t)row1 * OUTD + col] = make_float2(acc[nt][2], acc[nt][3]);
    }
}

// ---------------- combine: out = sum_rel num/Z + bias (float4) --------------
__global__ void __launch_bounds__(256) gat_combine(const float* __restrict__ bias,
                                                   float* __restrict__ out)
{
    const int idx4 = blockIdx.x * 256 + threadIdx.x;   // 65536 total
    const int base = idx4 * 4;
    const int i = base >> 6, cc = base & 63;
    float4 r = *(const float4*)(bias + cc);
#pragma unroll
    for (int rel = 0; rel < 2; ++rel) {
        float4 ns = make_float4(0.f, 0.f, 0.f, 0.f);
        float zs = 0.f;
#pragma unroll
        for (int ks = 0; ks < KSPLIT; ++ks) {
            float4 v = *(const float4*)&g_num[rel][ks][base];
            ns.x += v.x; ns.y += v.y; ns.z += v.z; ns.w += v.w;
            zs += g_Z[rel][ks][i];
        }
        float inv = (zs > 0.f) ? __frcp_rn(zs) : 0.f;
        r.x += ns.x * inv; r.y += ns.y * inv;
        r.z += ns.z * inv; r.w += ns.w * inv;
    }
    *(float4*)(out + base) = r;
}

// ---------------- launch ----------------------------------------------------
extern "C" void kernel_launch(void* const* d_in, const int* in_sizes, int n_in,
                              void* d_out, int out_size) {
    const float* H    = (const float*)d_in[0];
    const int*   A0   = (const int*)  d_in[1];
    const int*   A1   = (const int*)  d_in[2];
    const float* W0   = (const float*)d_in[3];
    const float* W1   = (const float*)d_in[4];
    const float* a0   = (const float*)d_in[5];
    const float* a1   = (const float*)d_in[6];
    const float* bias = (const float*)d_in[7];
    float* out = (float*)d_out;

    gat_prep<<<dim3(NN / 32, 2), 256>>>(H, W0, W1, a0, a1);
    gat_main<<<dim3(NN / MTILE, KSPLIT, 2), 256>>>(A0, A1);
    gat_combine<<<(NN * OUTD) / 1024, 256>>>(bias, out);
}